// round 10
// baseline (speedup 1.0000x reference)
#include <cuda_runtime.h>
#include <math.h>

#define NEXP 4
#define BATCH 16
#define CIN 3
#define HIMG 256
#define WIMG 256
#define HW 65536
#define DTOT 196608
#define HID 64

// expert-conv tile geometry
#define TW 64
#define TH 32
#define XSW 68                 // xs row stride (floats); cols col0-2 .. col0+65
#define XSH 36                 // rows row0-2 .. row0+33
#define HSW 68                 // hs cols (float2), hc in [0,68), valid [0,66)
#define HSH 34                 // hr in [0,34)
#define SM_XS 0
#define SM_HS (3*XSH*XSW)      // 7344 floats
#define SMEM_FLOATS (SM_HS + 2*HSH*HSW + 8)   // 11976 floats = 47904 B

typedef unsigned long long u64;

// ---------------- f32x2 packed-math helpers (sm_103a FFMA2) ----------------
__device__ __forceinline__ u64 pack2(float lo, float hi) {
    u64 r;
    asm("mov.b64 %0, {%1, %2};" : "=l"(r)
        : "r"(__float_as_uint(lo)), "r"(__float_as_uint(hi)));
    return r;
}
__device__ __forceinline__ u64 dup2(float v) {
    unsigned u = __float_as_uint(v);
    u64 r;
    asm("mov.b64 %0, {%1, %1};" : "=l"(r) : "r"(u));
    return r;
}
__device__ __forceinline__ void fma2(u64& d, u64 a, u64 b) {
    asm("fma.rn.f32x2 %0, %1, %2, %0;" : "+l"(d) : "l"(a), "l"(b));
}
__device__ __forceinline__ void unpack2(u64 v, float& lo, float& hi) {
    unsigned ulo, uhi;
    asm("mov.b64 {%0, %1}, %2;" : "=r"(ulo), "=r"(uhi) : "l"(v));
    lo = __uint_as_float(ulo); hi = __uint_as_float(uhi);
}

// ---------------- device scratch (no allocations allowed) ----------------
__device__ float g_tgate[BATCH][CIN][NEXP];
__device__ float g_tnoise[BATCH][CIN][NEXP];
__device__ float g_refsum[BATCH][CIN];
__device__ float g_gateval[BATCH][2];
__device__ int   g_topidx[BATCH][2];

__global__ void k_zero_scratch() {
    int t = threadIdx.x;
    if (t < BATCH * CIN * NEXP) {
        ((float*)g_tgate)[t]  = 0.f;
        ((float*)g_tnoise)[t] = 0.f;
    }
    if (t < BATCH * CIN) ((float*)g_refsum)[t] = 0.f;
}

__device__ __forceinline__ float warp_sum(float v) {
    #pragma unroll
    for (int o = 16; o > 0; o >>= 1) v += __shfl_down_sync(0xffffffffu, v, o);
    return v;
}

// ---------------- K1: per-(b,c) partial reductions ----------------
__global__ void k_partials(const float* __restrict__ x, const float* __restrict__ ref,
                           const float* __restrict__ wg, const float* __restrict__ wn) {
    int bc = blockIdx.x;
    int b = bc / CIN, c = bc - b * CIN;
    int base = blockIdx.y * 4096;
    const float*  xp  = x   + (size_t)b * DTOT + (size_t)c * HW + base;
    const float*  rp  = ref + (size_t)b * DTOT + (size_t)c * HW + base;
    const float4* wgp = (const float4*)wg + (size_t)c * HW + base;
    const float4* wnp = (const float4*)wn + (size_t)c * HW + base;

    float ag[4] = {0,0,0,0}, an[4] = {0,0,0,0}, ar = 0.f;
    for (int i = threadIdx.x; i < 4096; i += 256) {
        float xv = xp[i], rv = rp[i];
        float4 g4 = wgp[i], n4 = wnp[i];
        ag[0] += xv * g4.x; ag[1] += xv * g4.y; ag[2] += xv * g4.z; ag[3] += xv * g4.w;
        an[0] += xv * n4.x; an[1] += xv * n4.y; an[2] += xv * n4.z; an[3] += xv * n4.w;
        ar += rv;
    }
    int lane = threadIdx.x & 31;
    #pragma unroll
    for (int e = 0; e < 4; e++) {
        float s = warp_sum(ag[e]);
        if (lane == 0) atomicAdd(&g_tgate[b][c][e], s);
        s = warp_sum(an[e]);
        if (lane == 0) atomicAdd(&g_tnoise[b][c][e], s);
    }
    float s = warp_sum(ar);
    if (lane == 0) atomicAdd(&g_refsum[b][c], s);
}

// ---------------- K2: tiny gating kernel ----------------
// FFT branch collapsed to DC term: mean(irfft2_ortho(X)) = Re(X[0,0]) / 256
__global__ void k_gate(const float* __restrict__ noise,
                       const float* __restrict__ mw1, const float* __restrict__ mb1,
                       const float* __restrict__ mw2, const float* __restrict__ mb2,
                       const float* __restrict__ ehw, const float* __restrict__ ehb,
                       const float* __restrict__ fre,
                       float* __restrict__ out, int out_size) {
    __shared__ float sg[BATCH][NEXP];
    __shared__ float spb[BATCH][NEXP];
    int b = threadIdx.x;
    if (b < BATCH) {
        float s[CIN];
        #pragma unroll
        for (int c = 0; c < CIN; c++) s[c] = g_refsum[b][c] * (1.f / 256.f);

        float m1[6];
        #pragma unroll
        for (int o = 0; o < 6; o++) {
            float a = mb1[o];
            #pragma unroll
            for (int c = 0; c < 3; c++) a += (mw1[o*12 + c] + mw1[o*12 + 6 + c]) * s[c];
            m1[o] = fmaxf(a, 0.f);
        }
        float m2[6];
        #pragma unroll
        for (int o = 0; o < 6; o++) {
            float a = mb2[o];
            #pragma unroll
            for (int i = 0; i < 6; i++) a += mw2[o*6 + i] * m1[i];
            m2[o] = a;
        }
        float e0[6];
        #pragma unroll
        for (int o = 0; o < 6; o++) e0[o] = m2[o] * fre[(size_t)o * HIMG * (WIMG/2 + 1)];
        float eh[6];
        #pragma unroll
        for (int o = 0; o < 6; o++) {
            float a = ehb[o];
            #pragma unroll
            for (int i = 0; i < 6; i++) a += ehw[o*6 + i] * e0[i];
            eh[o] = fmaxf(a, 0.f);
        }
        float lg0 = eh[0] * (1.f/256.f), lg1 = eh[1] * (1.f/256.f), lg2 = eh[2] * (1.f/256.f);
        float mx = fmaxf(lg0, fmaxf(lg1, lg2));
        float ex0 = expf(lg0 - mx), ex1 = expf(lg1 - mx), ex2 = expf(lg2 - mx);
        float inv = 1.f / (ex0 + ex1 + ex2);
        float p[3] = {ex0 * inv, ex1 * inv, ex2 * inv};

        float cl[4], rn[4];
        #pragma unroll
        for (int e = 0; e < 4; e++) {
            float a = 0.f, bn = 0.f;
            #pragma unroll
            for (int c = 0; c < 3; c++) {
                float f = 1.f + p[c];
                a  += f * g_tgate[b][c][e];
                bn += f * g_tnoise[b][c][e];
            }
            cl[e] = a; rn[e] = bn;
        }
        float sd[4], nz[4];
        #pragma unroll
        for (int e = 0; e < 4; e++) {
            float r = rn[e];
            float sp = fmaxf(r, 0.f) + log1pf(expf(-fabsf(r)));
            sd[e] = sp + 0.01f;
            nz[e] = cl[e] + noise[b*4 + e] * sd[e];
        }
        float v[4]; int id[4];
        #pragma unroll
        for (int e = 0; e < 4; e++) { v[e] = nz[e]; id[e] = e; }
        #pragma unroll
        for (int s0 = 0; s0 < 3; s0++) {
            int best = s0;
            #pragma unroll
            for (int j = 0; j < 4; j++)
                if (j > s0 && v[j] > v[best]) best = j;
            float tv = v[s0]; v[s0] = v[best]; v[best] = tv;
            int   ti = id[s0]; id[s0] = id[best]; id[best] = ti;
        }
        float eA = expf(v[1] - v[0]);
        float g0 = 1.f / (1.f + eA), g1 = eA / (1.f + eA);
        g_gateval[b][0] = g0; g_gateval[b][1] = g1;
        g_topidx[b][0] = id[0]; g_topidx[b][1] = id[1];

        float gt[4] = {0,0,0,0};
        gt[id[0]] = g0; gt[id[1]] = g1;
        float thrin = v[2], throut = v[1];
        #pragma unroll
        for (int e = 0; e < 4; e++) {
            sg[b][e] = gt[e];
            float t = (nz[e] > thrin) ? (cl[e] - thrin) / sd[e] : (cl[e] - throut) / sd[e];
            spb[b][e] = normcdff(t);
        }
    }
    __syncthreads();
    if (threadIdx.x == 0) {
        float imp[4] = {0,0,0,0}, ld[4] = {0,0,0,0};
        for (int bb = 0; bb < BATCH; bb++)
            for (int e = 0; e < 4; e++) { imp[e] += sg[bb][e]; ld[e] += spb[bb][e]; }
        float loss = 0.f;
        #pragma unroll
        for (int which = 0; which < 2; which++) {
            float* vv = which ? ld : imp;
            float m = (vv[0] + vv[1] + vv[2] + vv[3]) * 0.25f;
            float va = 0.f;
            for (int e = 0; e < 4; e++) { float d = vv[e] - m; va += d * d; }
            va *= (1.f / 3.f);
            loss += va / (m * m + 1e-10f);
        }
        loss *= 0.01f;
        if (out_size > BATCH * HW) out[out_size - 1] = loss;
    }
}

// ---------------- K3: fused sparse expert convs (v3: packed f32x2 math) ----
// grid (4, 8, BATCH), 256 threads; 64x32 output tile; 2 experts (top-2).
// Both conv1 and conv2 process their 2 hidden channels per pass in ONE packed
// f32x2 lane pair via PTX fma.rn.f32x2 (FFMA2) — halves FMA issue count.
// conv1: weights packed (chA,chB) per-ci on the ALU pipe; x dup-packed.
// conv2: hs is float2(ch0,ch1) in SMEM -> loaded directly as packed operand.
__global__ void __launch_bounds__(256, 2)
k_expert(const float* __restrict__ x,
         const float* __restrict__ ew1, const float* __restrict__ eb1,
         const float* __restrict__ ew2, const float* __restrict__ eb2,
         float* __restrict__ out) {
    __shared__ float sm[SMEM_FLOATS];
    float*  xs = sm + SM_XS;               // [3][36][68]
    float2* hs = (float2*)(sm + SM_HS);    // [34][68] (ch0, ch1)

    int tid = threadIdx.x;
    int b = blockIdx.z;
    int row0 = blockIdx.y * TH, col0 = blockIdx.x * TW;
    int ie[2]   = {g_topidx[b][0], g_topidx[b][1]};
    float gv[2] = {g_gateval[b][0], g_gateval[b][1]};

    // ---- load x tile with halo 2 ----
    for (int t = tid; t < 3*XSH*XSW; t += 256) {
        int ci  = t / (XSH*XSW);
        int rem = t - ci*(XSH*XSW);
        int r = rem / XSW, c = rem - r*XSW;
        int gr = row0 - 2 + r, gc = col0 - 2 + c;
        float v = 0.f;
        if (gr >= 0 && gr < HIMG && gc >= 0 && gc < WIMG)
            v = x[((size_t)b*CIN + ci)*HW + gr*WIMG + gc];
        xs[t] = v;
    }
    __syncthreads();

    float bias2 = gv[0]*__ldg(&eb2[ie[0]]) + gv[1]*__ldg(&eb2[ie[1]]);
    u64 acc2p[2][4];            // packed (ch-partials summed at the end)
    #pragma unroll
    for (int it = 0; it < 2; it++)
        #pragma unroll
        for (int rr = 0; rr < 4; rr++) acc2p[it][rr] = 0ull;

    #pragma unroll 1
    for (int k = 0; k < 2; k++) {
        const float* w1base = ew1 + (size_t)ie[k] * (HID*27);
        const float* w2base = ew2 + (size_t)ie[k] * (HID*9);
        const float* b1base = eb1 + ie[k] * HID;
        float gk = gv[k];

        #pragma unroll 1
        for (int c0 = 0; c0 < HID; c0 += 2) {
            // ---- conv1 weights for 2 channels (global float2 broadcast) ----
            float w1r[54];
            {
                const float2* wp = (const float2*)(w1base + c0*27);
                #pragma unroll
                for (int j = 0; j < 27; j++) {
                    float2 wv = __ldg(wp + j);
                    w1r[2*j] = wv.x; w1r[2*j+1] = wv.y;
                }
            }
            u64 bbp = pack2(__ldg(b1base + c0), __ldg(b1base + c0 + 1));

            // ---- conv1: h region 34 rows x 68 cols, tasks 2r x 4c (289) ----
            #pragma unroll 1
            for (int t = tid; t < 17*17; t += 256) {
                int trg = t / 17, tcg = t - trg*17;
                int hr0 = 2*trg, hc0 = 4*tcg;
                u64 a01[2][4];
                #pragma unroll
                for (int o = 0; o < 2; o++)
                    #pragma unroll
                    for (int j = 0; j < 4; j++) a01[o][j] = bbp;

                #pragma unroll
                for (int ci = 0; ci < 3; ci++) {
                    // pack this ci's 9 weight pairs (chA lo, chB hi) — ALU pipe
                    u64 w2p[9];
                    #pragma unroll
                    for (int t9 = 0; t9 < 9; t9++)
                        w2p[t9] = pack2(w1r[ci*9 + t9], w1r[27 + ci*9 + t9]);

                    const float* bp = xs + ci*(XSH*XSW) + hr0*XSW + hc0;
                    #pragma unroll
                    for (int xr = 0; xr < 4; xr++) {
                        float4 v4 = *(const float4*)(bp + xr*XSW);
                        float2 v2 = *(const float2*)(bp + xr*XSW + 4);
                        u64 X[6];
                        X[0] = dup2(v4.x); X[1] = dup2(v4.y); X[2] = dup2(v4.z);
                        X[3] = dup2(v4.w); X[4] = dup2(v2.x); X[5] = dup2(v2.y);
                        #pragma unroll
                        for (int dr = 0; dr < 3; dr++) {
                            int o = xr - dr;
                            if (o == 0 || o == 1) {
                                #pragma unroll
                                for (int j = 0; j < 4; j++) {
                                    fma2(a01[o][j], w2p[dr*3 + 0], X[j]);
                                    fma2(a01[o][j], w2p[dr*3 + 1], X[j+1]);
                                    fma2(a01[o][j], w2p[dr*3 + 2], X[j+2]);
                                }
                            }
                        }
                    }
                }
                // store with image-boundary zero mask (conv2 sees zero padding)
                #pragma unroll
                for (int o = 0; o < 2; o++) {
                    int hr = hr0 + o;
                    int gr = row0 - 1 + hr;
                    bool rok = (gr >= 0) && (gr < HIMG);
                    #pragma unroll
                    for (int j = 0; j < 4; j++) {
                        int hc = hc0 + j;
                        int gc = col0 - 1 + hc;
                        bool ok = rok && (gc >= 0) && (gc < WIMG);
                        float lo, hi;
                        unpack2(a01[o][j], lo, hi);
                        float2 hv;
                        hv.x = ok ? fmaxf(lo, 0.f) : 0.f;
                        hv.y = ok ? fmaxf(hi, 0.f) : 0.f;
                        hs[hr*HSW + hc] = hv;
                    }
                }
            }
            __syncthreads();

            // ---- conv2: packed accumulate (gate folded into weights) ----
            u64 wq[9];
            {
                const float2* wp = (const float2*)(w2base + c0*9);  // c0 even -> 8B aligned
                float wtmp[18];
                #pragma unroll
                for (int j = 0; j < 9; j++) {
                    float2 wv = __ldg(wp + j);
                    wtmp[2*j] = wv.x; wtmp[2*j+1] = wv.y;
                }
                #pragma unroll
                for (int j = 0; j < 9; j++)
                    wq[j] = pack2(gk * wtmp[j], gk * wtmp[9 + j]);
            }
            #pragma unroll
            for (int it = 0; it < 2; it++) {
                int t = tid + it*256;
                int trg = t >> 6, c = t & 63;      // 8 row-groups x 64 cols
                const u64* hp = (const u64*)(hs + (4*trg)*HSW + c);
                u64 h2[6][3];
                #pragma unroll
                for (int r6 = 0; r6 < 6; r6++)
                    #pragma unroll
                    for (int dc = 0; dc < 3; dc++)
                        h2[r6][dc] = hp[r6*HSW + dc];
                #pragma unroll
                for (int rr = 0; rr < 4; rr++)
                    #pragma unroll
                    for (int dr = 0; dr < 3; dr++)
                        #pragma unroll
                        for (int dc = 0; dc < 3; dc++)
                            fma2(acc2p[it][rr], wq[dr*3 + dc], h2[rr+dr][dc]);
            }
            __syncthreads();
        }
    }

    // ---- write output (horizontal add of the packed channel partials) ----
    #pragma unroll
    for (int it = 0; it < 2; it++) {
        int t = tid + it*256;
        int trg = t >> 6, c = t & 63;
        #pragma unroll
        for (int rr = 0; rr < 4; rr++) {
            float lo, hi;
            unpack2(acc2p[it][rr], lo, hi);
            out[(size_t)b*HW + (row0 + 4*trg + rr)*WIMG + col0 + c] = lo + hi + bias2;
        }
    }
}

// ---------------- launch ----------------
extern "C" void kernel_launch(void* const* d_in, const int* in_sizes, int n_in,
                              void* d_out, int out_size) {
    const float* x     = (const float*)d_in[0];
    const float* ref   = (const float*)d_in[1];
    const float* noise = (const float*)d_in[2];
    const float* mw1   = (const float*)d_in[3];
    const float* mb1   = (const float*)d_in[4];
    const float* mw2   = (const float*)d_in[5];
    const float* mb2   = (const float*)d_in[6];
    const float* ehw   = (const float*)d_in[7];
    const float* ehb   = (const float*)d_in[8];
    const float* fre   = (const float*)d_in[9];
    const float* wg    = (const float*)d_in[10];
    const float* wn    = (const float*)d_in[11];
    const float* ew1   = (const float*)d_in[12];
    const float* eb1   = (const float*)d_in[13];
    const float* ew2   = (const float*)d_in[14];
    const float* eb2   = (const float*)d_in[15];
    float* out = (float*)d_out;

    k_zero_scratch<<<1, 256>>>();
    k_partials<<<dim3(BATCH * CIN, 16), 256>>>(x, ref, wg, wn);
    k_gate<<<1, 16>>>(noise, mw1, mb1, mw2, mb2, ehw, ehb, fre, out, out_size);
    k_expert<<<dim3(4, 8, BATCH), 256>>>(x, ew1, eb1, ew2, eb2, out);
}